// round 11
// baseline (speedup 1.0000x reference)
#include <cuda_runtime.h>
#include <cuda_bf16.h>
#include <cstdint>

#define DDIM   128
#define ROWS_W 16                    // rows per warp-tile
#define NTH    320
#define NW     10                    // warps per CTA

// ---- smem layout (bytes) ----
#define A_STRIDE 272                 // bf16 row: 256 data + 16 pad
#define WH_OFF   0                   // W_hi  128 rows
#define WL_OFF   (128 * A_STRIDE)    // 34816
#define AW_SZ    (ROWS_W * A_STRIDE) // 4352 per warp per buffer
#define AH_OFF   (2 * 128 * A_STRIDE)          // 69632
#define AL_OFF   (AH_OFF + NW * AW_SZ)         // 113152
#define BS_OFF   (AL_OFF + NW * AW_SZ)         // 156672 (bias 128 f32)
#define SMEM_TOTAL (BS_OFF + 512)              // 157184

__device__ __forceinline__ uint32_t s2u(const void* p) {
    return (uint32_t)__cvta_generic_to_shared(p);
}
__device__ __forceinline__ void mma_bf16(float& d0, float& d1, float& d2, float& d3,
                                         uint32_t a0, uint32_t a1, uint32_t a2, uint32_t a3,
                                         uint32_t b0, uint32_t b1) {
    asm volatile("mma.sync.aligned.m16n8k16.row.col.f32.bf16.bf16.f32 "
                 "{%0,%1,%2,%3}, {%4,%5,%6,%7}, {%8,%9}, {%0,%1,%2,%3};"
                 : "+f"(d0), "+f"(d1), "+f"(d2), "+f"(d3)
                 : "r"(a0), "r"(a1), "r"(a2), "r"(a3), "r"(b0), "r"(b1));
}
__device__ __forceinline__ void ldmx4(uint32_t& r0, uint32_t& r1, uint32_t& r2, uint32_t& r3,
                                      uint32_t addr) {
    asm volatile("ldmatrix.sync.aligned.m8n8.x4.shared.b16 {%0,%1,%2,%3}, [%4];"
                 : "=r"(r0), "=r"(r1), "=r"(r2), "=r"(r3) : "r"(addr));
}
__device__ __forceinline__ void split2(float2 x, uint32_t& h, uint32_t& l) {
    __nv_bfloat16 h0 = __float2bfloat16_rn(x.x);
    __nv_bfloat16 h1 = __float2bfloat16_rn(x.y);
    __nv_bfloat16 l0 = __float2bfloat16_rn(x.x - __bfloat162float(h0));
    __nv_bfloat16 l1 = __float2bfloat16_rn(x.y - __bfloat162float(h1));
    __nv_bfloat162 hh = __halves2bfloat162(h0, h1);
    __nv_bfloat162 ll = __halves2bfloat162(l0, l1);
    h = *(uint32_t*)&hh;
    l = *(uint32_t*)&ll;
}
__device__ __forceinline__ uint2 hi4(float4 x) {
    __nv_bfloat162 a = __halves2bfloat162(__float2bfloat16_rn(x.x), __float2bfloat16_rn(x.y));
    __nv_bfloat162 b = __halves2bfloat162(__float2bfloat16_rn(x.z), __float2bfloat16_rn(x.w));
    return make_uint2(*(uint32_t*)&a, *(uint32_t*)&b);
}
__device__ __forceinline__ uint2 lo4(float4 x) {
    float lx = x.x - __bfloat162float(__float2bfloat16_rn(x.x));
    float ly = x.y - __bfloat162float(__float2bfloat16_rn(x.y));
    float lz = x.z - __bfloat162float(__float2bfloat16_rn(x.z));
    float lw = x.w - __bfloat162float(__float2bfloat16_rn(x.w));
    __nv_bfloat162 a = __halves2bfloat162(__float2bfloat16_rn(lx), __float2bfloat16_rn(ly));
    __nv_bfloat162 b = __halves2bfloat162(__float2bfloat16_rn(lz), __float2bfloat16_rn(lw));
    return make_uint2(*(uint32_t*)&a, *(uint32_t*)&b);
}

extern "C" __global__ void __launch_bounds__(NTH, 1)
hh_hmma_kernel(const float* __restrict__ z, const float* __restrict__ v,
               const float* __restrict__ W, const float* __restrict__ b,
               float* __restrict__ out, int B)
{
    extern __shared__ char sm[];
    float* bs = (float*)(sm + BS_OFF);

    const int tid  = threadIdx.x;
    const int w    = tid >> 5;
    const int lane = tid & 31;
    const int qk   = (lane & 3) * 2;
    const int qr   = lane >> 2;

    const uint32_t sm_u = s2u(sm);
    // A (warp-private) ldmatrix base: row = lane&15, chunk = lane>>4
    const uint32_t ahib = sm_u + AH_OFF + (uint32_t)w * AW_SZ
                        + (uint32_t)(lane & 15) * A_STRIDE + (uint32_t)(lane >> 4) * 16;
    const uint32_t alob = ahib + (uint32_t)(AL_OFF - AH_OFF);
    // W ldmatrix base: x4 covers (n=16, k=16); nt2 selects which 16 cols
    const int mi = lane >> 3;
    const int r8 = lane & 7;
    const uint32_t whib = sm_u + WH_OFF
                        + (uint32_t)((mi >> 1) * 8 + r8) * A_STRIDE
                        + (uint32_t)(mi & 1) * 16;
    const uint32_t wlob = whib + (uint32_t)(WL_OFF - WH_OFF);
    // convert STS base: row j -> j*A_STRIDE, lane covers 8B
    const uint32_t cvt_hi = sm_u + AH_OFF + (uint32_t)w * AW_SZ + (uint32_t)lane * 8;
    const uint32_t cvt_lo = cvt_hi + (uint32_t)(AL_OFF - AH_OFF);

    // ---- one-time: W -> hi/lo smem; bias -> smem ----
    for (int it = 0; it < 26; it++) {
        int p = tid + it * NTH;
        if (p < 128 * 64) {
            int row = p >> 6;
            int kp  = p & 63;
            float2 x = *(const float2*)&W[row * DDIM + kp * 2];
            uint32_t h, l;
            split2(x, h, l);
            *(uint32_t*)(sm + WH_OFF + row * A_STRIDE + kp * 4) = h;
            *(uint32_t*)(sm + WL_OFF + row * A_STRIDE + kp * 4) = l;
        }
    }
    if (tid < 128) bs[tid] = b[tid];
    __syncthreads();      // last CTA-wide barrier

    const int nwt    = B / ROWS_W;                 // 32768 warp-tiles
    const int stride = (int)gridDim.x * NW;
    const int t0     = (int)blockIdx.x * NW + w;

    // ---- prologue: v(t0) into registers ----
    float4 vreg[16];
    if (t0 < nwt) {
        const float* src = v + (size_t)t0 * ROWS_W * DDIM;
        #pragma unroll
        for (int j = 0; j < 16; j++)
            vreg[j] = *(const float4*)(src + (size_t)(lane + j * 32) * 4);
    }

    for (int t = t0; t < nwt; t += stride) {
        const size_t rb = (size_t)t * ROWS_W * DDIM;

        // ---- convert v regs -> private A hi/lo (row j, cols lane*4) ----
        #pragma unroll
        for (int j = 0; j < 16; j++) {
            uint32_t dst = (uint32_t)j * A_STRIDE;
            *(uint2*)(size_t)0;   // (no-op placeholder removed below)
            ((uint2*)0); // dummy
        }
        // (real stores)
        #pragma unroll
        for (int j = 0; j < 16; j++) {
            uint32_t dsel = (uint32_t)j * A_STRIDE;
            asm volatile("st.shared.v2.b32 [%0], {%1, %2};" ::
                         "r"(cvt_hi + dsel), "r"(hi4(vreg[j]).x), "r"(hi4(vreg[j]).y) : "memory");
            asm volatile("st.shared.v2.b32 [%0], {%1, %2};" ::
                         "r"(cvt_lo + dsel), "r"(lo4(vreg[j]).x), "r"(lo4(vreg[j]).y) : "memory");
        }
        __syncwarp();

        // ---- issue v(next) LDGs; fly under MMA+epilogue ----
        const int nxt = t + stride;
        if (nxt < nwt) {
            const float* src = v + (size_t)nxt * ROWS_W * DDIM;
            #pragma unroll
            for (int j = 0; j < 16; j++)
                vreg[j] = *(const float4*)(src + (size_t)(lane + j * 32) * 4);
        }

        // ---- MMA: m16 x n128 x k128, 3-pass split bf16 ----
        float acc[16][4];
        #pragma unroll
        for (int nt = 0; nt < 16; nt++)
            #pragma unroll
            for (int i = 0; i < 4; i++) acc[nt][i] = 0.f;

        #pragma unroll
        for (int kk = 0; kk < 8; kk++) {
            uint32_t ah0, ah1, ah2, ah3, al0, al1, al2, al3;
            ldmx4(ah0, ah1, ah2, ah3, ahib + (uint32_t)kk * 32);
            ldmx4(al0, al1, al2, al3, alob + (uint32_t)kk * 32);
            #pragma unroll
            for (int nt2 = 0; nt2 < 8; nt2++) {
                uint32_t h0, h1, h2, h3, l0, l1, l2, l3;
                const uint32_t woff = (uint32_t)nt2 * (16 * A_STRIDE) + (uint32_t)kk * 32;
                ldmx4(h0, h1, h2, h3, whib + woff);
                ldmx4(l0, l1, l2, l3, wlob + woff);
                const int nt = nt2 * 2;
                mma_bf16(acc[nt][0], acc[nt][1], acc[nt][2], acc[nt][3],
                         ah0, ah1, ah2, ah3, h0, h1);
                mma_bf16(acc[nt][0], acc[nt][1], acc[nt][2], acc[nt][3],
                         ah0, ah1, ah2, ah3, l0, l1);
                mma_bf16(acc[nt][0], acc[nt][1], acc[nt][2], acc[nt][3],
                         al0, al1, al2, al3, h0, h1);
                mma_bf16(acc[nt+1][0], acc[nt+1][1], acc[nt+1][2], acc[nt+1][3],
                         ah0, ah1, ah2, ah3, h2, h3);
                mma_bf16(acc[nt+1][0], acc[nt+1][1], acc[nt+1][2], acc[nt+1][3],
                         ah0, ah1, ah2, ah3, l2, l3);
                mma_bf16(acc[nt+1][0], acc[nt+1][1], acc[nt+1][2], acc[nt+1][3],
                         al0, al1, al2, al3, h2, h3);
            }
        }
        __syncwarp();   // A reads done before next-tile convert overwrites

        // ---- dot/norm: rows (qr, qr+8), quad-shfl reduce ----
        const float* zr0 = z + rb + (size_t)qr * DDIM;
        const float* zr1 = zr0 + 8 * DDIM;
        float d0 = 0.f, m0 = 0.f, d1 = 0.f, m1 = 0.f;
        #pragma unroll
        for (int nt = 0; nt < 16; nt++) {
            float2 bb = *(const float2*)&bs[nt * 8 + qk];
            float2 za = *(const float2*)&zr0[nt * 8 + qk];
            float2 zb = *(const float2*)&zr1[nt * 8 + qk];
            float vn0 = acc[nt][0] + bb.x;
            float vn1 = acc[nt][1] + bb.y;
            float vn2 = acc[nt][2] + bb.x;
            float vn3 = acc[nt][3] + bb.y;
            d0 = fmaf(vn0, za.x, d0); d0 = fmaf(vn1, za.y, d0);
            m0 = fmaf(vn0, vn0, m0);  m0 = fmaf(vn1, vn1, m0);
            d1 = fmaf(vn2, zb.x, d1); d1 = fmaf(vn3, zb.y, d1);
            m1 = fmaf(vn2, vn2, m1);  m1 = fmaf(vn3, vn3, m1);
        }
        d0 += __shfl_xor_sync(0xffffffffu, d0, 1);
        d0 += __shfl_xor_sync(0xffffffffu, d0, 2);
        m0 += __shfl_xor_sync(0xffffffffu, m0, 1);
        m0 += __shfl_xor_sync(0xffffffffu, m0, 2);
        d1 += __shfl_xor_sync(0xffffffffu, d1, 1);
        d1 += __shfl_xor_sync(0xffffffffu, d1, 2);
        m1 += __shfl_xor_sync(0xffffffffu, m1, 1);
        m1 += __shfl_xor_sync(0xffffffffu, m1, 2);
        const float s0 = 2.0f * d0 / m0;
        const float s1 = 2.0f * d1 / m1;

        // ---- reflect + store (z reload hits L1) ----
        float* or0 = out + rb + (size_t)qr * DDIM;
        float* or1 = or0 + 8 * DDIM;
        #pragma unroll
        for (int nt = 0; nt < 16; nt++) {
            float2 bb = *(const float2*)&bs[nt * 8 + qk];
            float2 za = *(const float2*)&zr0[nt * 8 + qk];
            float2 zb = *(const float2*)&zr1[nt * 8 + qk];
            float2 o;
            o.x = za.x - s0 * (acc[nt][0] + bb.x);
            o.y = za.y - s0 * (acc[nt][1] + bb.y);
            *(float2*)&or0[nt * 8 + qk] = o;
            o.x = zb.x - s1 * (acc[nt][2] + bb.x);
            o.y = zb.y - s1 * (acc[nt][3] + bb.y);
            *(float2*)&or1[nt * 8 + qk] = o;
        }
    }
}

extern "C" void kernel_launch(void* const* d_in, const int* in_sizes, int n_in,
                              void* d_out, int out_size) {
    const float* z = (const float*)d_in[0];
    const float* v = (const float*)d_in[1];
    const float* W = (const float*)d_in[2];
    const float* b = (const float*)d_in[3];
    float* out = (float*)d_out;

    const int B = in_sizes[0] / DDIM;

    cudaFuncSetAttribute(hh_hmma_kernel, cudaFuncAttributeMaxDynamicSharedMemorySize, SMEM_TOTAL);
    hh_hmma_kernel<<<148, NTH, SMEM_TOTAL>>>(z, v, W, b, out, B);
}

// round 12
// speedup vs baseline: 1.1734x; 1.1734x over previous
#include <cuda_runtime.h>
#include <cuda_bf16.h>
#include <cstdint>

#define DDIM   128
#define TILE_M 64
#define NTH    256

// ---- smem layout (bytes) ----
#define A_STRIDE 272                     // bf16 row: 256 data + 16 pad
#define AH_OFF   0                       // A_hi 64 rows
#define AL_OFF   (TILE_M * A_STRIDE)     // 17408
#define WH_OFF   (2 * TILE_M * A_STRIDE) // 34816
#define WL_OFF   (WH_OFF + 128 * A_STRIDE)  // 69632
#define PSD_OFF  (WL_OFF + 128 * A_STRIDE)  // 104448  [4][64] f32
#define PSN_OFF  (PSD_OFF + 4 * TILE_M * 4)
#define SC_OFF   (PSN_OFF + 4 * TILE_M * 4)  // [64]
#define BS_OFF   (SC_OFF + TILE_M * 4)       // bias 128 f32
#define SMEM_TOTAL (BS_OFF + 512)            // 107008

__device__ __forceinline__ uint32_t s2u(const void* p) {
    return (uint32_t)__cvta_generic_to_shared(p);
}
__device__ __forceinline__ void mma_bf16(float& d0, float& d1, float& d2, float& d3,
                                         uint32_t a0, uint32_t a1, uint32_t a2, uint32_t a3,
                                         uint32_t b0, uint32_t b1) {
    asm volatile("mma.sync.aligned.m16n8k16.row.col.f32.bf16.bf16.f32 "
                 "{%0,%1,%2,%3}, {%4,%5,%6,%7}, {%8,%9}, {%0,%1,%2,%3};"
                 : "+f"(d0), "+f"(d1), "+f"(d2), "+f"(d3)
                 : "r"(a0), "r"(a1), "r"(a2), "r"(a3), "r"(b0), "r"(b1));
}
__device__ __forceinline__ void ldmx4(uint32_t& r0, uint32_t& r1, uint32_t& r2, uint32_t& r3,
                                      uint32_t addr) {
    asm volatile("ldmatrix.sync.aligned.m8n8.x4.shared.b16 {%0,%1,%2,%3}, [%4];"
                 : "=r"(r0), "=r"(r1), "=r"(r2), "=r"(r3) : "r"(addr));
}
__device__ __forceinline__ void split2(float2 x, uint32_t& h, uint32_t& l) {
    __nv_bfloat16 h0 = __float2bfloat16_rn(x.x);
    __nv_bfloat16 h1 = __float2bfloat16_rn(x.y);
    __nv_bfloat16 l0 = __float2bfloat16_rn(x.x - __bfloat162float(h0));
    __nv_bfloat16 l1 = __float2bfloat16_rn(x.y - __bfloat162float(h1));
    __nv_bfloat162 hh = __halves2bfloat162(h0, h1);
    __nv_bfloat162 ll = __halves2bfloat162(l0, l1);
    h = *(uint32_t*)&hh;
    l = *(uint32_t*)&ll;
}
__device__ __forceinline__ uint2 hi4(float4 x) {
    __nv_bfloat162 a = __halves2bfloat162(__float2bfloat16_rn(x.x), __float2bfloat16_rn(x.y));
    __nv_bfloat162 b = __halves2bfloat162(__float2bfloat16_rn(x.z), __float2bfloat16_rn(x.w));
    return make_uint2(*(uint32_t*)&a, *(uint32_t*)&b);
}
__device__ __forceinline__ uint2 lo4(float4 x) {
    float lx = x.x - __bfloat162float(__float2bfloat16_rn(x.x));
    float ly = x.y - __bfloat162float(__float2bfloat16_rn(x.y));
    float lz = x.z - __bfloat162float(__float2bfloat16_rn(x.z));
    float lw = x.w - __bfloat162float(__float2bfloat16_rn(x.w));
    __nv_bfloat162 a = __halves2bfloat162(__float2bfloat16_rn(lx), __float2bfloat16_rn(ly));
    __nv_bfloat162 b = __halves2bfloat162(__float2bfloat16_rn(lz), __float2bfloat16_rn(lw));
    return make_uint2(*(uint32_t*)&a, *(uint32_t*)&b);
}

extern "C" __global__ void __launch_bounds__(NTH, 2)
hh_hmma_kernel(const float* __restrict__ z, const float* __restrict__ v,
               const float* __restrict__ W, const float* __restrict__ b,
               float* __restrict__ out, int B)
{
    extern __shared__ char sm[];
    float* psd = (float*)(sm + PSD_OFF);
    float* psn = (float*)(sm + PSN_OFF);
    float* scs = (float*)(sm + SC_OFF);
    float* bs  = (float*)(sm + BS_OFF);

    const int tid  = threadIdx.x;
    const int w    = tid >> 5;
    const int lane = tid & 31;
    const int cg   = w & 3;          // column group (32 cols)
    const int mg   = w >> 2;         // row group (32 rows)
    const int n0   = cg * 32;
    const int qk   = (lane & 3) * 2;
    const int qr   = lane >> 2;

    const uint32_t sm_u = s2u(sm);
    const uint32_t ahib = sm_u + AH_OFF
                        + (uint32_t)(mg * 32 + (lane & 15)) * A_STRIDE
                        + (uint32_t)(lane >> 4) * 16;
    const uint32_t alob = ahib + (uint32_t)(AL_OFF - AH_OFF);
    const int mi = lane >> 3;
    const int r8 = lane & 7;
    const uint32_t whib0 = sm_u + WH_OFF
                         + (uint32_t)(n0 + (mi >> 1) * 8 + r8) * A_STRIDE
                         + (uint32_t)(mi & 1) * 16;
    const uint32_t whib1 = whib0 + 16u * A_STRIDE;
    const uint32_t wlob0 = whib0 + (uint32_t)(WL_OFF - WH_OFF);
    const uint32_t wlob1 = whib1 + (uint32_t)(WL_OFF - WH_OFF);

    // ---- one-time: W -> hi/lo smem; bias ----
    #pragma unroll
    for (int it = 0; it < 32; it++) {
        int p   = tid + it * NTH;         // pair index over 128x64
        int row = p >> 6;
        int kp  = p & 63;
        float2 x = *(const float2*)&W[row * DDIM + kp * 2];
        uint32_t h, l;
        split2(x, h, l);
        *(uint32_t*)(sm + WH_OFF + row * A_STRIDE + kp * 4) = h;
        *(uint32_t*)(sm + WL_OFF + row * A_STRIDE + kp * 4) = l;
    }
    if (tid < 128) bs[tid] = b[tid];
    float2 bias[4];
    #pragma unroll
    for (int nt = 0; nt < 4; nt++) bias[nt] = *(const float2*)&b[n0 + nt * 8 + qk];
    __syncthreads();

    const int ntiles = B / TILE_M;           // 8192
    const int G = (int)gridDim.x;

    // ---- prologue: v(t0) into registers ----
    float4 vreg[8];
    if ((int)blockIdx.x < ntiles) {
        const float* src = v + (size_t)blockIdx.x * TILE_M * DDIM;
        #pragma unroll
        for (int j = 0; j < 8; j++)
            vreg[j] = *(const float4*)(src + (size_t)(tid + j * NTH) * 4);
    }

    for (int tile = blockIdx.x; tile < ntiles; tile += G) {
        const size_t tb = (size_t)tile * TILE_M * DDIM;
        const int nxt = tile + G;

        // ---- convert v regs -> A hi/lo smem ----
        #pragma unroll
        for (int j = 0; j < 8; j++) {
            int c   = tid + j * NTH;
            int row = c >> 5;
            int k   = (c & 31) * 4;
            *(uint2*)(sm + AH_OFF + row * A_STRIDE + k * 2) = hi4(vreg[j]);
            *(uint2*)(sm + AL_OFF + row * A_STRIDE + k * 2) = lo4(vreg[j]);
        }
        __syncthreads();

        // ---- issue v(next) LDGs; fly under MMA ----
        if (nxt < ntiles) {
            const float* src = v + (size_t)nxt * TILE_M * DDIM;
            #pragma unroll
            for (int j = 0; j < 8; j++)
                vreg[j] = *(const float4*)(src + (size_t)(tid + j * NTH) * 4);
        }

        // ---- MMA: 3-pass split bf16 ----
        float acc[2][4][4];
        #pragma unroll
        for (int mt = 0; mt < 2; mt++)
            #pragma unroll
            for (int nt = 0; nt < 4; nt++)
                #pragma unroll
                for (int i = 0; i < 4; i++) acc[mt][nt][i] = 0.f;

        #pragma unroll
        for (int kk = 0; kk < 8; kk++) {
            uint32_t bhf[8], blf[8];
            ldmx4(bhf[0], bhf[1], bhf[2], bhf[3], whib0 + (uint32_t)kk * 32);
            ldmx4(bhf[4], bhf[5], bhf[6], bhf[7], whib1 + (uint32_t)kk * 32);
            ldmx4(blf[0], blf[1], blf[2], blf[3], wlob0 + (uint32_t)kk * 32);
            ldmx4(blf[4], blf[5], blf[6], blf[7], wlob1 + (uint32_t)kk * 32);
            #pragma unroll
            for (int mt = 0; mt < 2; mt++) {
                uint32_t ah0, ah1, ah2, ah3, al0, al1, al2, al3;
                const uint32_t off = (uint32_t)mt * (16 * A_STRIDE) + (uint32_t)kk * 32;
                ldmx4(ah0, ah1, ah2, ah3, ahib + off);
                ldmx4(al0, al1, al2, al3, alob + off);
                #pragma unroll
                for (int nt = 0; nt < 4; nt++) {
                    mma_bf16(acc[mt][nt][0], acc[mt][nt][1], acc[mt][nt][2], acc[mt][nt][3],
                             ah0, ah1, ah2, ah3, bhf[nt * 2], bhf[nt * 2 + 1]);
                    mma_bf16(acc[mt][nt][0], acc[mt][nt][1], acc[mt][nt][2], acc[mt][nt][3],
                             ah0, ah1, ah2, ah3, blf[nt * 2], blf[nt * 2 + 1]);
                    mma_bf16(acc[mt][nt][0], acc[mt][nt][1], acc[mt][nt][2], acc[mt][nt][3],
                             al0, al1, al2, al3, bhf[nt * 2], bhf[nt * 2 + 1]);
                }
            }
        }
        __syncthreads();    // A free for next convert

        // ---- dot/norm per row: z fragments via direct LDG (32B sectors) ----
        #pragma unroll
        for (int mt = 0; mt < 2; mt++) {
            const int rt = mg * 32 + mt * 16 + qr;
            const float* zr0 = z + tb + (size_t)rt * DDIM;
            const float* zr1 = zr0 + 8 * DDIM;
            float d0 = 0.f, m0 = 0.f, d1 = 0.f, m1 = 0.f;
            #pragma unroll
            for (int nt = 0; nt < 4; nt++) {
                float2 za = *(const float2*)&zr0[n0 + nt * 8 + qk];
                float2 zb = *(const float2*)&zr1[n0 + nt * 8 + qk];
                float vn0 = acc[mt][nt][0] + bias[nt].x;
                float vn1 = acc[mt][nt][1] + bias[nt].y;
                float vn2 = acc[mt][nt][2] + bias[nt].x;
                float vn3 = acc[mt][nt][3] + bias[nt].y;
                d0 = fmaf(vn0, za.x, d0); d0 = fmaf(vn1, za.y, d0);
                m0 = fmaf(vn0, vn0, m0);  m0 = fmaf(vn1, vn1, m0);
                d1 = fmaf(vn2, zb.x, d1); d1 = fmaf(vn3, zb.y, d1);
                m1 = fmaf(vn2, vn2, m1);  m1 = fmaf(vn3, vn3, m1);
            }
            d0 += __shfl_xor_sync(0xffffffffu, d0, 1);
            d0 += __shfl_xor_sync(0xffffffffu, d0, 2);
            m0 += __shfl_xor_sync(0xffffffffu, m0, 1);
            m0 += __shfl_xor_sync(0xffffffffu, m0, 2);
            d1 += __shfl_xor_sync(0xffffffffu, d1, 1);
            d1 += __shfl_xor_sync(0xffffffffu, d1, 2);
            m1 += __shfl_xor_sync(0xffffffffu, m1, 1);
            m1 += __shfl_xor_sync(0xffffffffu, m1, 2);
            if ((lane & 3) == 0) {
                psd[cg * TILE_M + rt]     = d0;
                psd[cg * TILE_M + rt + 8] = d1;
                psn[cg * TILE_M + rt]     = m0;
                psn[cg * TILE_M + rt + 8] = m1;
            }
        }
        __syncthreads();

        if (tid < TILE_M) {
            float dt = psd[tid] + psd[TILE_M + tid] + psd[2 * TILE_M + tid] + psd[3 * TILE_M + tid];
            float nm = psn[tid] + psn[TILE_M + tid] + psn[2 * TILE_M + tid] + psn[3 * TILE_M + tid];
            scs[tid] = 2.0f * dt / nm;
        }
        __syncthreads();

        // ---- reflect + store (z reload: L1 hit) ----
        #pragma unroll
        for (int mt = 0; mt < 2; mt++) {
            const int rt = mg * 32 + mt * 16 + qr;
            const float s0 = scs[rt];
            const float s1 = scs[rt + 8];
            const float* zr0 = z + tb + (size_t)rt * DDIM;
            const float* zr1 = zr0 + 8 * DDIM;
            float* or0 = out + tb + (size_t)rt * DDIM;
            float* or1 = or0 + 8 * DDIM;
            #pragma unroll
            for (int nt = 0; nt < 4; nt++) {
                float2 za = *(const float2*)&zr0[n0 + nt * 8 + qk];
                float2 zb = *(const float2*)&zr1[n0 + nt * 8 + qk];
                float2 o;
                o.x = za.x - s0 * (acc[mt][nt][0] + bias[nt].x);
                o.y = za.y - s0 * (acc[mt][nt][1] + bias[nt].y);
                *(float2*)&or0[n0 + nt * 8 + qk] = o;
                o.x = zb.x - s1 * (acc[mt][nt][2] + bias[nt].x);
                o.y = zb.y - s1 * (acc[mt][nt][3] + bias[nt].y);
                *(float2*)&or1[n0 + nt * 8 + qk] = o;
            }
        }
        // no end-of-loop barrier needed: next A write is separated from this
        // tile's A reads by the post-MMA + post-dot + post-scale barriers.
    }
}

extern "C" void kernel_launch(void* const* d_in, const int* in_sizes, int n_in,
                              void* d_out, int out_size) {
    const float* z = (const float*)d_in[0];
    const float* v = (const float*)d_in[1];
    const float* W = (const float*)d_in[2];
    const float* b = (const float*)d_in[3];
    float* out = (float*)d_out;

    const int B = in_sizes[0] / DDIM;

    cudaFuncSetAttribute(hh_hmma_kernel, cudaFuncAttributeMaxDynamicSharedMemorySize, SMEM_TOTAL);
    hh_hmma_kernel<<<296, NTH, SMEM_TOTAL>>>(z, v, W, b, out, B);
}

// round 13
// speedup vs baseline: 1.5642x; 1.3331x over previous
#include <cuda_runtime.h>
#include <cuda_bf16.h>
#include <cstdint>

#define DDIM   128
#define TILE_M 64
#define NTH    512

// ---- smem layout (bytes) ----
#define A_STRIDE 272                     // bf16 row: 256 data + 16 pad
#define AH_OFF   0                       // A_hi 64 rows
#define AL_OFF   17408                   // A_lo
#define WH_OFF   34816                   // W_hi 128 rows
#define WL_OFF   69632                   // W_lo
#define D_OFF    104448                  // D buffers: 2 x 64 x 132 f32
#define DST      132                     // D row stride (floats)
#define DBUF_SZ  (TILE_M * DST * 4)      // 33792
#define BS_OFF   (D_OFF + 2 * DBUF_SZ)   // 172032 bias
#define SMEM_TOTAL (BS_OFF + 512)        // 172544

// named barrier ids
#define BC1 1
#define BC2 2
#define DFULL0 3
#define DFULL1 4
#define DFREE0 5
#define DFREE1 6

__device__ __forceinline__ uint32_t s2u(const void* p) {
    return (uint32_t)__cvta_generic_to_shared(p);
}
__device__ __forceinline__ void bsync(int id, int cnt) {
    asm volatile("bar.sync %0, %1;" :: "r"(id), "r"(cnt) : "memory");
}
__device__ __forceinline__ void barrive(int id, int cnt) {
    asm volatile("bar.arrive %0, %1;" :: "r"(id), "r"(cnt) : "memory");
}
__device__ __forceinline__ void mma_bf16(float& d0, float& d1, float& d2, float& d3,
                                         uint32_t a0, uint32_t a1, uint32_t a2, uint32_t a3,
                                         uint32_t b0, uint32_t b1) {
    asm volatile("mma.sync.aligned.m16n8k16.row.col.f32.bf16.bf16.f32 "
                 "{%0,%1,%2,%3}, {%4,%5,%6,%7}, {%8,%9}, {%0,%1,%2,%3};"
                 : "+f"(d0), "+f"(d1), "+f"(d2), "+f"(d3)
                 : "r"(a0), "r"(a1), "r"(a2), "r"(a3), "r"(b0), "r"(b1));
}
__device__ __forceinline__ void ldmx4(uint32_t& r0, uint32_t& r1, uint32_t& r2, uint32_t& r3,
                                      uint32_t addr) {
    asm volatile("ldmatrix.sync.aligned.m8n8.x4.shared.b16 {%0,%1,%2,%3}, [%4];"
                 : "=r"(r0), "=r"(r1), "=r"(r2), "=r"(r3) : "r"(addr));
}
__device__ __forceinline__ void split2(float2 x, uint32_t& h, uint32_t& l) {
    __nv_bfloat16 h0 = __float2bfloat16_rn(x.x);
    __nv_bfloat16 h1 = __float2bfloat16_rn(x.y);
    __nv_bfloat16 l0 = __float2bfloat16_rn(x.x - __bfloat162float(h0));
    __nv_bfloat16 l1 = __float2bfloat16_rn(x.y - __bfloat162float(h1));
    __nv_bfloat162 hh = __halves2bfloat162(h0, h1);
    __nv_bfloat162 ll = __halves2bfloat162(l0, l1);
    h = *(uint32_t*)&hh;
    l = *(uint32_t*)&ll;
}
__device__ __forceinline__ uint2 hi4(float4 x) {
    __nv_bfloat162 a = __halves2bfloat162(__float2bfloat16_rn(x.x), __float2bfloat16_rn(x.y));
    __nv_bfloat162 b = __halves2bfloat162(__float2bfloat16_rn(x.z), __float2bfloat16_rn(x.w));
    return make_uint2(*(uint32_t*)&a, *(uint32_t*)&b);
}
__device__ __forceinline__ uint2 lo4(float4 x) {
    float lx = x.x - __bfloat162float(__float2bfloat16_rn(x.x));
    float ly = x.y - __bfloat162float(__float2bfloat16_rn(x.y));
    float lz = x.z - __bfloat162float(__float2bfloat16_rn(x.z));
    float lw = x.w - __bfloat162float(__float2bfloat16_rn(x.w));
    __nv_bfloat162 a = __halves2bfloat162(__float2bfloat16_rn(lx), __float2bfloat16_rn(ly));
    __nv_bfloat162 b = __halves2bfloat162(__float2bfloat16_rn(lz), __float2bfloat16_rn(lw));
    return make_uint2(*(uint32_t*)&a, *(uint32_t*)&b);
}

extern "C" __global__ void __launch_bounds__(NTH, 1)
hh_ws_kernel(const float* __restrict__ z, const float* __restrict__ v,
             const float* __restrict__ W, const float* __restrict__ b,
             float* __restrict__ out, int B)
{
    extern __shared__ char sm[];
    float* bs = (float*)(sm + BS_OFF);

    const int tid  = threadIdx.x;
    const int w    = tid >> 5;
    const int lane = tid & 31;

    // ---- one-time: W -> hi/lo smem; bias (all 512 threads) ----
    #pragma unroll
    for (int it = 0; it < 16; it++) {
        int p   = tid + it * NTH;        // pair index over 128x64
        int row = p >> 6;
        int kp  = p & 63;
        float2 x = *(const float2*)&W[row * DDIM + kp * 2];
        uint32_t h, l;
        split2(x, h, l);
        *(uint32_t*)(sm + WH_OFF + row * A_STRIDE + kp * 4) = h;
        *(uint32_t*)(sm + WL_OFF + row * A_STRIDE + kp * 4) = l;
    }
    if (tid < 128) bs[tid] = b[tid];
    __syncthreads();

    const int ntiles = B / TILE_M;
    const int G = (int)gridDim.x;
    const uint32_t sm_u = s2u(sm);

    if (tid < 256) {
        // ================= COMPUTE ROLE (warps 0-7) =================
        const int ct   = tid;
        const int cw   = w;
        const int cg   = cw & 3;         // 32-col group
        const int mg   = cw >> 2;        // 32-row group
        const int n0   = cg * 32;
        const int qk   = (lane & 3) * 2;
        const int qr   = lane >> 2;

        const uint32_t ahib = sm_u + AH_OFF
                            + (uint32_t)(mg * 32 + (lane & 15)) * A_STRIDE
                            + (uint32_t)(lane >> 4) * 16;
        const uint32_t alob = ahib + (uint32_t)(AL_OFF - AH_OFF);
        const int mi = lane >> 3;
        const int r8 = lane & 7;
        const uint32_t whib0 = sm_u + WH_OFF
                             + (uint32_t)(n0 + (mi >> 1) * 8 + r8) * A_STRIDE
                             + (uint32_t)(mi & 1) * 16;
        const uint32_t whib1 = whib0 + 16u * A_STRIDE;
        const uint32_t wlob0 = whib0 + (uint32_t)(WL_OFF - WH_OFF);
        const uint32_t wlob1 = whib1 + (uint32_t)(WL_OFF - WH_OFF);

        // prologue: v(first tile)
        float4 vreg[8];
        if ((int)blockIdx.x < ntiles) {
            const float* src = v + (size_t)blockIdx.x * TILE_M * DDIM;
            #pragma unroll
            for (int j = 0; j < 8; j++)
                vreg[j] = *(const float4*)(src + (size_t)(ct + j * 256) * 4);
        }

        int q = 0;
        for (int tile = blockIdx.x; tile < ntiles; tile += G, q ^= 1) {
            bsync(BC1, 256);             // prev MMA reads of A complete

            // convert v -> A hi/lo
            #pragma unroll
            for (int j = 0; j < 8; j++) {
                int c   = ct + j * 256;
                int row = c >> 5;
                int k   = (c & 31) * 4;
                *(uint2*)(sm + AH_OFF + row * A_STRIDE + k * 2) = hi4(vreg[j]);
                *(uint2*)(sm + AL_OFF + row * A_STRIDE + k * 2) = lo4(vreg[j]);
            }
            // stage v(next): flies under MMA
            const int nxt = tile + G;
            if (nxt < ntiles) {
                const float* src = v + (size_t)nxt * TILE_M * DDIM;
                #pragma unroll
                for (int j = 0; j < 8; j++)
                    vreg[j] = *(const float4*)(src + (size_t)(ct + j * 256) * 4);
            }
            bsync(BC2, 256);             // A full

            float acc[2][4][4];
            #pragma unroll
            for (int mt = 0; mt < 2; mt++)
                #pragma unroll
                for (int nt = 0; nt < 4; nt++)
                    #pragma unroll
                    for (int i = 0; i < 4; i++) acc[mt][nt][i] = 0.f;

            #pragma unroll
            for (int kk = 0; kk < 8; kk++) {
                uint32_t bhf[8], blf[8];
                ldmx4(bhf[0], bhf[1], bhf[2], bhf[3], whib0 + (uint32_t)kk * 32);
                ldmx4(bhf[4], bhf[5], bhf[6], bhf[7], whib1 + (uint32_t)kk * 32);
                ldmx4(blf[0], blf[1], blf[2], blf[3], wlob0 + (uint32_t)kk * 32);
                ldmx4(blf[4], blf[5], blf[6], blf[7], wlob1 + (uint32_t)kk * 32);
                #pragma unroll
                for (int mt = 0; mt < 2; mt++) {
                    uint32_t ah0, ah1, ah2, ah3, al0, al1, al2, al3;
                    const uint32_t off = (uint32_t)mt * (16 * A_STRIDE) + (uint32_t)kk * 32;
                    ldmx4(ah0, ah1, ah2, ah3, ahib + off);
                    ldmx4(al0, al1, al2, al3, alob + off);
                    #pragma unroll
                    for (int nt = 0; nt < 4; nt++) {
                        mma_bf16(acc[mt][nt][0], acc[mt][nt][1], acc[mt][nt][2], acc[mt][nt][3],
                                 ah0, ah1, ah2, ah3, bhf[nt * 2], bhf[nt * 2 + 1]);
                        mma_bf16(acc[mt][nt][0], acc[mt][nt][1], acc[mt][nt][2], acc[mt][nt][3],
                                 ah0, ah1, ah2, ah3, blf[nt * 2], blf[nt * 2 + 1]);
                        mma_bf16(acc[mt][nt][0], acc[mt][nt][1], acc[mt][nt][2], acc[mt][nt][3],
                                 al0, al1, al2, al3, bhf[nt * 2], bhf[nt * 2 + 1]);
                    }
                }
            }

            // D[q] must be free (epi finished reading it two iterations ago)
            bsync(q ? DFREE1 : DFREE0, 512);
            float* D = (float*)(sm + D_OFF + q * DBUF_SZ);
            #pragma unroll
            for (int mt = 0; mt < 2; mt++) {
                const int rt = mg * 32 + mt * 16 + qr;
                #pragma unroll
                for (int nt = 0; nt < 4; nt++) {
                    *(float2*)&D[rt * DST + n0 + nt * 8 + qk] =
                        make_float2(acc[mt][nt][0], acc[mt][nt][1]);
                    *(float2*)&D[(rt + 8) * DST + n0 + nt * 8 + qk] =
                        make_float2(acc[mt][nt][2], acc[mt][nt][3]);
                }
            }
            barrive(q ? DFULL1 : DFULL0, 512);
        }
    } else {
        // ================= EPILOGUE ROLE (warps 8-15) =================
        const int ew = w - 8;            // 0..7
        const int row0 = ew * 8;         // 8 rows per warp
        float4 bsr;                      // bias for cols lane*4..+3
        bsr = *(const float4*)&bs[lane * 4];

        // both D buffers start free
        barrive(DFREE0, 512);
        barrive(DFREE1, 512);

        int q = 0;
        for (int tile = blockIdx.x; tile < ntiles; tile += G, q ^= 1) {
            const size_t tb = (size_t)tile * TILE_M * DDIM;

            // load z rows early (overlaps compute MMA)
            float4 zreg[8];
            #pragma unroll
            for (int r = 0; r < 8; r++)
                zreg[r] = *(const float4*)(z + tb + (size_t)(row0 + r) * DDIM + lane * 4);

            bsync(q ? DFULL1 : DFULL0, 512);
            const float* D = (const float*)(sm + D_OFF + q * DBUF_SZ);

            #pragma unroll
            for (int r = 0; r < 8; r++) {
                const int row = row0 + r;
                float4 d4 = *(const float4*)&D[row * DST + lane * 4];
                float vn0 = d4.x + bsr.x;
                float vn1 = d4.y + bsr.y;
                float vn2 = d4.z + bsr.z;
                float vn3 = d4.w + bsr.w;
                float4 z4 = zreg[r];
                float dt = vn0 * z4.x + vn1 * z4.y + vn2 * z4.z + vn3 * z4.w;
                float nm = vn0 * vn0 + vn1 * vn1 + vn2 * vn2 + vn3 * vn3;
                #pragma unroll
                for (int s = 16; s; s >>= 1) {
                    dt += __shfl_xor_sync(0xffffffffu, dt, s);
                    nm += __shfl_xor_sync(0xffffffffu, nm, s);
                }
                const float sc = 2.0f * dt / nm;
                float4 o;
                o.x = z4.x - sc * vn0;
                o.y = z4.y - sc * vn1;
                o.z = z4.z - sc * vn2;
                o.w = z4.w - sc * vn3;
                *(float4*)(out + tb + (size_t)row * DDIM + lane * 4) = o;
            }
            barrive(q ? DFREE1 : DFREE0, 512);
        }
    }
}

extern "C" void kernel_launch(void* const* d_in, const int* in_sizes, int n_in,
                              void* d_out, int out_size) {
    const float* z = (const float*)d_in[0];
    const float* v = (const float*)d_in[1];
    const float* W = (const float*)d_in[2];
    const float* b = (const float*)d_in[3];
    float* out = (float*)d_out;

    const int B = in_sizes[0] / DDIM;

    cudaFuncSetAttribute(hh_ws_kernel, cudaFuncAttributeMaxDynamicSharedMemorySize, SMEM_TOTAL);
    hh_ws_kernel<<<148, NTH, SMEM_TOTAL>>>(z, v, W, b, out, B);
}